// round 4
// baseline (speedup 1.0000x reference)
#include <cuda_runtime.h>
#include <cuda_bf16.h>
#include <cstdio>

// Problem constants
#define PB 2
#define PT 2048
#define PC 1024
#define PH 16
#define PD 64
#define PM (PB * PT)          // 4096
#define QKV_N (3 * PH * PD)   // 3072

// Scratch (allocation-free rule: __device__ globals)
__device__ float g_q[PB * PH * PT * PD];
__device__ float g_k[PB * PH * PT * PD];
__device__ float g_v[PB * PH * PT * PD];
__device__ float g_y[PM * PC];

// ---------------------------------------------------------------------------
// Fast exp: FFMA-only (avoid MUFU bottleneck; 67M exps in attention).
// exp(x) = 2^(x*log2e); degree-5 Taylor of 2^f on [0,1), rel err ~8e-5.
// ---------------------------------------------------------------------------
__device__ __forceinline__ float fast_exp(float x) {
    float y = fmaxf(x * 1.4426950408889634f, -126.0f);
    float n = floorf(y);
    float f = y - n;
    float p = 0.0013333558f;
    p = fmaf(p, f, 0.0096181291f);
    p = fmaf(p, f, 0.0555041087f);
    p = fmaf(p, f, 0.2402265069f);
    p = fmaf(p, f, 0.6931471806f);
    p = fmaf(p, f, 1.0f);
    int e = (int)n;
    return p * __int_as_float((e + 127) << 23);
}

// ---------------------------------------------------------------------------
// Kernel 1: fused QKV projection. NT GEMM: out[m,n] = sum_c x[m,c]*W[n,c]
// A = x [4096,1024] row-major (K contig), B = w_{q,k,v} [1024,1024] (K contig).
// Block tile 128x128, K-tile 8, 256 threads, 8x8 per thread.
// Writes q/k/v in [b][h][t][d] layout.
// ---------------------------------------------------------------------------
__global__ __launch_bounds__(256) void qkv_proj_kernel(
    const float* __restrict__ x, const float* __restrict__ wq,
    const float* __restrict__ wk, const float* __restrict__ wv) {
    __shared__ float As[8][128];
    __shared__ float Bs[8][128];

    const int tid = threadIdx.x;
    const int bm = blockIdx.x * 128;
    const int bn = blockIdx.y * 128;          // 0..3071
    const int which = bn >> 10;               // 0=q,1=k,2=v (128 | 1024)
    const int nbase = bn & 1023;
    const float* w = (which == 0) ? wq : (which == 1) ? wk : wv;
    float* outp = (which == 0) ? g_q : (which == 1) ? g_k : g_v;

    const int l_row = tid >> 1;               // 0..127
    const int l_k = (tid & 1) << 2;           // 0 or 4
    const int tx = tid & 15;
    const int ty = tid >> 4;

    float acc[8][8];
#pragma unroll
    for (int i = 0; i < 8; i++)
#pragma unroll
        for (int j = 0; j < 8; j++) acc[i][j] = 0.f;

    const float* aptr = x + (size_t)(bm + l_row) * PC + l_k;
    const float* bptr = w + (size_t)(nbase + l_row) * PC + l_k;

    for (int k0 = 0; k0 < PC; k0 += 8) {
        float4 av = *(const float4*)(aptr + k0);
        float4 bv = *(const float4*)(bptr + k0);
        As[l_k + 0][l_row] = av.x; As[l_k + 1][l_row] = av.y;
        As[l_k + 2][l_row] = av.z; As[l_k + 3][l_row] = av.w;
        Bs[l_k + 0][l_row] = bv.x; Bs[l_k + 1][l_row] = bv.y;
        Bs[l_k + 2][l_row] = bv.z; Bs[l_k + 3][l_row] = bv.w;
        __syncthreads();
#pragma unroll
        for (int kk = 0; kk < 8; kk++) {
            float a[8], b[8];
            *(float4*)&a[0] = *(const float4*)&As[kk][ty * 8];
            *(float4*)&a[4] = *(const float4*)&As[kk][ty * 8 + 4];
            *(float4*)&b[0] = *(const float4*)&Bs[kk][tx * 8];
            *(float4*)&b[4] = *(const float4*)&Bs[kk][tx * 8 + 4];
#pragma unroll
            for (int i = 0; i < 8; i++)
#pragma unroll
                for (int j = 0; j < 8; j++) acc[i][j] = fmaf(a[i], b[j], acc[i][j]);
        }
        __syncthreads();
    }

    // scatter into [b][h][t][d]
#pragma unroll
    for (int i = 0; i < 8; i++) {
        int m = bm + ty * 8 + i;
        int b = m >> 11;        // /2048
        int t = m & 2047;
#pragma unroll
        for (int j = 0; j < 8; j++) {
            int n = nbase + tx * 8 + j;
            int h = n >> 6;
            int d = n & 63;
            outp[((size_t)((b << 4) + h) * PT + t) * PD + d] = acc[i][j];
        }
    }
}

// ---------------------------------------------------------------------------
// Kernel 2: causal flash attention, fp32.
// Block = 256 threads, 64-query tile per block, 64-key tiles.
// Smem: Qs[d][q], KP[d][kcol] (reused as P^T[kcol][q]), Vs[k][d], pitch 68.
// Online softmax state m/l per row, shfl reductions (4 threads per row).
// ---------------------------------------------------------------------------
#define APITCH 68
#define ATTN_SMEM_BYTES ((3 * 64 * APITCH + 3 * 64) * 4)

__global__ __launch_bounds__(256) void attn_kernel() {
    extern __shared__ float smem_raw[];
    float (*Qs)[APITCH] = (float(*)[APITCH])smem_raw;
    float (*KP)[APITCH] = (float(*)[APITCH])(smem_raw + 64 * APITCH);
    float (*Vs)[APITCH] = (float(*)[APITCH])(smem_raw + 2 * 64 * APITCH);
    float* m_s = smem_raw + 3 * 64 * APITCH;
    float* l_s = m_s + 64;
    float* corr_s = l_s + 64;

    const int tid = threadIdx.x;
    const int tx = tid & 15, ty = tid >> 4;
    const int bh = blockIdx.y;                 // b*16 + h
    const int q0 = blockIdx.x << 6;
    const size_t base = (size_t)bh * PT * PD;
    const float* qg = g_q + base;
    const float* kg = g_k + base;
    const float* vg = g_v + base;

    // Load Q tile transposed: Qs[d][q]
    {
        int r = tid >> 2;
        int dbase = (tid & 3) << 4;
        const float* row = qg + (size_t)(q0 + r) * PD + dbase;
#pragma unroll
        for (int i = 0; i < 16; i += 4) {
            float4 v = *(const float4*)(row + i);
            Qs[dbase + i + 0][r] = v.x;
            Qs[dbase + i + 1][r] = v.y;
            Qs[dbase + i + 2][r] = v.z;
            Qs[dbase + i + 3][r] = v.w;
        }
    }
    if (tid < 64) { m_s[tid] = -1e30f; l_s[tid] = 0.f; }

    float o[4][4];
#pragma unroll
    for (int i = 0; i < 4; i++)
#pragma unroll
        for (int j = 0; j < 4; j++) o[i][j] = 0.f;

    const int jmax = q0 >> 6;
    for (int jt = 0; jt <= jmax; jt++) {
        const int k0 = jt << 6;
        // Load K transposed (KP[d][kcol]) and V natural (Vs[k][d])
        {
            int r = tid >> 2;
            int dbase = (tid & 3) << 4;
            const float* krow = kg + (size_t)(k0 + r) * PD + dbase;
            const float* vrow = vg + (size_t)(k0 + r) * PD + dbase;
#pragma unroll
            for (int i = 0; i < 16; i += 4) {
                float4 kv = *(const float4*)(krow + i);
                KP[dbase + i + 0][r] = kv.x;
                KP[dbase + i + 1][r] = kv.y;
                KP[dbase + i + 2][r] = kv.z;
                KP[dbase + i + 3][r] = kv.w;
                *(float4*)&Vs[r][dbase + i] = *(const float4*)(vrow + i);
            }
        }
        __syncthreads();

        // S = Q K^T : thread computes 4x4 (q rows ty*4.., k cols tx*4..)
        float s[4][4];
#pragma unroll
        for (int i = 0; i < 4; i++)
#pragma unroll
            for (int j = 0; j < 4; j++) s[i][j] = 0.f;
#pragma unroll 16
        for (int d = 0; d < 64; d++) {
            const float4 aq = *(const float4*)&Qs[d][ty << 2];
            const float4 bk = *(const float4*)&KP[d][tx << 2];
            const float av[4] = {aq.x, aq.y, aq.z, aq.w};
            const float bv[4] = {bk.x, bk.y, bk.z, bk.w};
#pragma unroll
            for (int i = 0; i < 4; i++)
#pragma unroll
                for (int j = 0; j < 4; j++) s[i][j] = fmaf(av[i], bv[j], s[i][j]);
        }
        __syncthreads();  // everyone done reading KP before it becomes P^T

        // scale + causal mask, store transposed: KP[kcol][qrow]
        const float scale = 0.125f;  // 1/sqrt(64)
#pragma unroll
        for (int i = 0; i < 4; i++) {
            int qi = q0 + (ty << 2) + i;
#pragma unroll
            for (int j = 0; j < 4; j++) {
                int ki = k0 + (tx << 2) + j;
                float v = s[i][j] * scale;
                if (ki > qi) v = -1e30f;
                KP[(tx << 2) + j][(ty << 2) + i] = v;
            }
        }
        __syncthreads();

        // Online softmax: 4 threads per row, shfl-reduce max & sum
        {
            int r = tid >> 2, p = tid & 3;
            int cbase = p << 4;
            float tmax = -1e30f;
#pragma unroll
            for (int c = 0; c < 16; c++) tmax = fmaxf(tmax, KP[cbase + c][r]);
            tmax = fmaxf(tmax, __shfl_xor_sync(0xffffffffu, tmax, 1));
            tmax = fmaxf(tmax, __shfl_xor_sync(0xffffffffu, tmax, 2));
            float mold = m_s[r];
            float newm = fmaxf(mold, tmax);
            float psum = 0.f;
#pragma unroll
            for (int c = 0; c < 16; c++) {
                float pv = fast_exp(KP[cbase + c][r] - newm);
                KP[cbase + c][r] = pv;
                psum += pv;
            }
            psum += __shfl_xor_sync(0xffffffffu, psum, 1);
            psum += __shfl_xor_sync(0xffffffffu, psum, 2);
            if (p == 0) {
                float cr = fast_exp(mold - newm);
                corr_s[r] = cr;
                l_s[r] = l_s[r] * cr + psum;
                m_s[r] = newm;
            }
        }
        __syncthreads();

        // O = O*corr + P V
#pragma unroll
        for (int i = 0; i < 4; i++) {
            float cf = corr_s[(ty << 2) + i];
#pragma unroll
            for (int j = 0; j < 4; j++) o[i][j] *= cf;
        }
#pragma unroll 16
        for (int kk = 0; kk < 64; kk++) {
            const float4 ap = *(const float4*)&KP[kk][ty << 2];
            const float4 bp = *(const float4*)&Vs[kk][tx << 2];
            const float av[4] = {ap.x, ap.y, ap.z, ap.w};
            const float bv[4] = {bp.x, bp.y, bp.z, bp.w};
#pragma unroll
            for (int i = 0; i < 4; i++)
#pragma unroll
                for (int j = 0; j < 4; j++) o[i][j] = fmaf(av[i], bv[j], o[i][j]);
        }
        __syncthreads();  // protect KP/Vs for next tile
    }

    // Epilogue: normalize + store y in [b][t][h*64+d]
    const int b = bh >> 4;
    const int h = bh & 15;
#pragma unroll
    for (int i = 0; i < 4; i++) {
        int q = q0 + (ty << 2) + i;
        float inv = 1.f / l_s[(ty << 2) + i];
#pragma unroll
        for (int j = 0; j < 4; j++) {
            int d = (tx << 2) + j;
            g_y[((size_t)b * PT + q) * PC + h * PD + d] = o[i][j] * inv;
        }
    }
}

// ---------------------------------------------------------------------------
// Kernel 3: output projection. NN GEMM: out[m,n] = sum_k y[m,k]*wo[k,n]
// ---------------------------------------------------------------------------
__global__ __launch_bounds__(256) void out_proj_kernel(
    const float* __restrict__ wo, float* __restrict__ out) {
    __shared__ float As[8][128];
    __shared__ float Bs[8][128];

    const int tid = threadIdx.x;
    const int bm = blockIdx.x * 128;
    const int bn = blockIdx.y * 128;
    const int a_row = tid >> 1;
    const int a_k = (tid & 1) << 2;
    const int b_r = tid >> 5;             // 0..7
    const int b_c = (tid & 31) << 2;      // 0..124
    const int tx = tid & 15, ty = tid >> 4;

    float acc[8][8];
#pragma unroll
    for (int i = 0; i < 8; i++)
#pragma unroll
        for (int j = 0; j < 8; j++) acc[i][j] = 0.f;

    const float* aptr = g_y + (size_t)(bm + a_row) * PC + a_k;
    const float* bptr = wo + (size_t)b_r * PC + bn + b_c;

    for (int k0 = 0; k0 < PC; k0 += 8) {
        float4 av = *(const float4*)(aptr + k0);
        As[a_k + 0][a_row] = av.x; As[a_k + 1][a_row] = av.y;
        As[a_k + 2][a_row] = av.z; As[a_k + 3][a_row] = av.w;
        float4 bv = *(const float4*)(bptr + (size_t)k0 * PC);
        *(float4*)&Bs[b_r][b_c] = bv;
        __syncthreads();
#pragma unroll
        for (int kk = 0; kk < 8; kk++) {
            float a[8], b[8];
            *(float4*)&a[0] = *(const float4*)&As[kk][ty * 8];
            *(float4*)&a[4] = *(const float4*)&As[kk][ty * 8 + 4];
            *(float4*)&b[0] = *(const float4*)&Bs[kk][tx * 8];
            *(float4*)&b[4] = *(const float4*)&Bs[kk][tx * 8 + 4];
#pragma unroll
            for (int i = 0; i < 8; i++)
#pragma unroll
                for (int j = 0; j < 8; j++) acc[i][j] = fmaf(a[i], b[j], acc[i][j]);
        }
        __syncthreads();
    }

#pragma unroll
    for (int i = 0; i < 8; i++) {
        int m = bm + ty * 8 + i;
        float* orow = out + (size_t)m * PC + bn + tx * 8;
        *(float4*)&orow[0] = *(float4*)&acc[i][0];
        *(float4*)&orow[4] = *(float4*)&acc[i][4];
    }
}

// ---------------------------------------------------------------------------
extern "C" void kernel_launch(void* const* d_in, const int* in_sizes, int n_in,
                              void* d_out, int out_size) {
    const float* x  = (const float*)d_in[0];
    const float* wq = (const float*)d_in[1];
    const float* wk = (const float*)d_in[2];
    const float* wv = (const float*)d_in[3];
    const float* wo = (const float*)d_in[4];
    float* out = (float*)d_out;

    cudaFuncSetAttribute(attn_kernel,
                         cudaFuncAttributeMaxDynamicSharedMemorySize,
                         ATTN_SMEM_BYTES);

    qkv_proj_kernel<<<dim3(PM / 128, QKV_N / 128), 256>>>(x, wq, wk, wv);
    attn_kernel<<<dim3(PT / 64, PB * PH), 256, ATTN_SMEM_BYTES>>>();
    out_proj_kernel<<<dim3(PM / 128, PC / 128), 256>>>(wo, out);
}

// round 10
// speedup vs baseline: 1.3795x; 1.3795x over previous
#include <cuda_runtime.h>
#include <cuda_bf16.h>
#include <cstdint>

// Problem constants
#define PB 2
#define PT 2048
#define PC 1024
#define PH 16
#define PD 64
#define PM (PB * PT)          // 4096
#define KTOT 3072             // [hi | lo | hi] (A-side) / [hi | hi | lo] (B-side)

// ---------------------------------------------------------------------------
// Device scratch (allocation-free rule: __device__ globals)
// ---------------------------------------------------------------------------
__device__ float g_q[PB * PH * PT * PD];
__device__ float g_k[PB * PH * PT * PD];
__device__ float g_v[PB * PH * PT * PD];
__device__ __nv_bfloat16 g_xs[(size_t)PM * KTOT];        // x  [hi|lo|hi]
__device__ __nv_bfloat16 g_ws[(size_t)3 * PC * KTOT];    // wq|wk|wv [hi|hi|lo]
__device__ __nv_bfloat16 g_ys[(size_t)PM * KTOT];        // y  [hi|lo|hi]
__device__ __nv_bfloat16 g_wos[(size_t)PC * KTOT];       // wo^T [hi|hi|lo]

// ---------------------------------------------------------------------------
// PTX helpers — plain compute_103-safe (sm_80-era): mma.sync bf16, ldmatrix,
// cp.async. NO tcgen05 (gated behind sm_103a PTX target the harness can't emit).
// ---------------------------------------------------------------------------
__device__ __forceinline__ uint32_t smem_u32(const void* p) {
    uint32_t a;
    asm("{ .reg .u64 t; cvta.to.shared.u64 t, %1; cvt.u32.u64 %0, t; }"
        : "=r"(a) : "l"(p));
    return a;
}
#define CP_ASYNC16(dst, src) \
    asm volatile("cp.async.cg.shared.global [%0], [%1], 16;" :: "r"(dst), "l"(src))
#define CP_COMMIT() asm volatile("cp.async.commit_group;" ::: "memory")
#define CP_WAIT2()  asm volatile("cp.async.wait_group 2;" ::: "memory")

__device__ __forceinline__ void ldmx4(uint32_t* r, uint32_t a) {
    asm volatile("ldmatrix.sync.aligned.m8n8.x4.shared.b16 {%0,%1,%2,%3}, [%4];"
                 : "=r"(r[0]), "=r"(r[1]), "=r"(r[2]), "=r"(r[3]) : "r"(a));
}
__device__ __forceinline__ void mma16816(float* c, const uint32_t* a,
                                         const uint32_t* b) {
    asm volatile(
        "mma.sync.aligned.m16n8k16.row.col.f32.bf16.bf16.f32 "
        "{%0,%1,%2,%3}, {%4,%5,%6,%7}, {%8,%9}, {%0,%1,%2,%3};"
        : "+f"(c[0]), "+f"(c[1]), "+f"(c[2]), "+f"(c[3])
        : "r"(a[0]), "r"(a[1]), "r"(a[2]), "r"(a[3]), "r"(b[0]), "r"(b[1]));
}

// ---------------------------------------------------------------------------
// fp32 -> hi (top-16-bit truncation) + lo (bf16_rn of residual).
// A-side (sel 0, g_xs): segments [hi | lo | hi]
// B-side (sel 1, g_ws): segments [hi | hi | lo]
// Aligned K-concat dot = hi.hi + lo.hi + hi.lo  (lo.lo ~2^-16 dropped).
// ---------------------------------------------------------------------------
__global__ __launch_bounds__(256) void split_kernel(
    const float* __restrict__ src, int sel, int row_off, int n4) {
    int i = blockIdx.x * 256 + threadIdx.x;
    if (i >= n4) return;
    int m = i >> 8, c4 = i & 255;            // 256 float4 per 1024-wide row
    float4 a = ((const float4*)src)[i];
    uint32_t ax = __float_as_uint(a.x), ay = __float_as_uint(a.y);
    uint32_t az = __float_as_uint(a.z), aw = __float_as_uint(a.w);
    uint32_t h01 = __byte_perm(ax, ay, 0x7632);
    uint32_t h23 = __byte_perm(az, aw, 0x7632);
    float l0 = a.x - __uint_as_float(ax & 0xFFFF0000u);
    float l1 = a.y - __uint_as_float(ay & 0xFFFF0000u);
    float l2 = a.z - __uint_as_float(az & 0xFFFF0000u);
    float l3 = a.w - __uint_as_float(aw & 0xFFFF0000u);
    uint32_t p01, p23;
    asm("cvt.rn.bf16x2.f32 %0, %1, %2;" : "=r"(p01) : "f"(l1), "f"(l0));
    asm("cvt.rn.bf16x2.f32 %0, %1, %2;" : "=r"(p23) : "f"(l3), "f"(l2));
    uint2* dst = (uint2*)((sel == 0) ? (void*)g_xs : (void*)g_ws)
                 + (size_t)(row_off + m) * (KTOT / 4);
    uint2 hv = make_uint2(h01, h23);
    uint2 lv = make_uint2(p01, p23);
    dst[c4] = hv;                                   // seg0: hi
    if (sel == 0) {
        dst[256 + c4] = lv;                         // seg1: lo (A-side)
        dst[512 + c4] = hv;                         // seg2: hi
    } else {
        dst[256 + c4] = hv;                         // seg1: hi (B-side)
        dst[512 + c4] = lv;                         // seg2: lo
    }
}

// wo [k=1024][n=1024] -> g_wos [n][hi | hi | lo]
__global__ void transpose_split_wo(const float* __restrict__ wo) {
    __shared__ float t[32][33];
    int bx = blockIdx.x * 32;   // n block
    int by = blockIdx.y * 32;   // k block
    int tx = threadIdx.x, ty = threadIdx.y;   // 32 x 8
#pragma unroll
    for (int i = 0; i < 32; i += 8)
        t[ty + i][tx] = wo[(size_t)(by + ty + i) * PC + bx + tx];
    __syncthreads();
#pragma unroll
    for (int i = 0; i < 32; i += 8) {
        float v = t[tx][ty + i];                       // k=by+tx, n=bx+ty+i
        size_t o = (size_t)(bx + ty + i) * KTOT + by + tx;
        uint32_t u = __float_as_uint(v);
        unsigned short hb = (unsigned short)(u >> 16);
        __nv_bfloat16 lb =
            __float2bfloat16(v - __uint_as_float(u & 0xFFFF0000u));
        ((unsigned short*)g_wos)[o] = hb;              // seg0 hi
        ((unsigned short*)g_wos)[o + 1024] = hb;       // seg1 hi
        g_wos[o + 2048] = lb;                          // seg2 lo
    }
}

// ---------------------------------------------------------------------------
// bf16 NT GEMM via mma.sync: C[128x128] = A[128xKTOT] * B[128xKTOT]^T.
// 256 threads = 8 warps (4 M x 2 N), warp tile 32x64, K-stage 64, 3-stage
// cp.async pipeline, XOR-swizzled 128B smem rows (conflict-free ldmatrix).
// MODE 0: A=g_xs, B=g_ws, scatter fp32 to g_q/g_k/g_v [b][h][t][d]
// MODE 1: A=g_ys, B=g_wos, write fp32 d_out row-major
// ---------------------------------------------------------------------------
#define GSTG 32768                 // one stage: A 16KB + B 16KB
#define GEMM_SMEM (3 * GSTG)       // 96KB

template <int MODE>
__global__ __launch_bounds__(256) void gemm_kernel(float* __restrict__ outp) {
    extern __shared__ char smem[];
    const uint32_t sb = smem_u32(smem);
    const int tid = threadIdx.x;
    const int wid = tid >> 5, l = tid & 31;
    const int wm = wid & 3, wn = wid >> 2;
    const int bm = blockIdx.x * 128, bn = blockIdx.y * 128;

    const __nv_bfloat16* Ag = (MODE == 0) ? g_xs : g_ys;
    const __nv_bfloat16* Bg = (MODE == 0) ? g_ws : g_wos;

    // cp.async roles: thread t loads row t/2, 4 x 16B chunks at half (t&1)
    const int lrow = tid >> 1, lh = tid & 1;
    const __nv_bfloat16* aRow = Ag + (size_t)(bm + lrow) * KTOT + lh * 32;
    const __nv_bfloat16* bRow = Bg + (size_t)(bn + lrow) * KTOT + lh * 32;
    const uint32_t dRow = (uint32_t)lrow * 128;
    const uint32_t dXor = (uint32_t)(lrow & 7) << 4;

    // ldmatrix per-lane bases (row%8 invariant across fragments -> const XOR)
    const uint32_t aBase = (uint32_t)(wm * 32 + (l & 15)) * 128;
    const uint32_t aC = (uint32_t)(l >> 4) << 4;
    const uint32_t lX = (uint32_t)(l & 7) << 4;
    const uint32_t bBase = 16384u + (uint32_t)(wn * 64 + (l & 7) + ((l >> 4) << 3)) * 128;
    const uint32_t bC = (uint32_t)((l >> 3) & 1) << 4;

    float acc[2][8][4];
#pragma unroll
    for (int i = 0; i < 2; i++)
#pragma unroll
        for (int j = 0; j < 8; j++)
#pragma unroll
            for (int r = 0; r < 4; r++) acc[i][j][r] = 0.f;

#define LOAD_STAGE(s, k0)                                                     \
    do {                                                                      \
        uint32_t da = sb + (s) * GSTG + dRow;                                 \
        uint32_t db = da + 16384;                                             \
        const __nv_bfloat16* pa = aRow + (k0);                                \
        const __nv_bfloat16* pb = bRow + (k0);                                \
        _Pragma("unroll")                                                     \
        for (int i = 0; i < 4; i++) {                                         \
            uint32_t c = (uint32_t)(((lh * 4 + i) * 16)) ^ dXor;              \
            CP_ASYNC16(da + c, pa + i * 8);                                   \
            CP_ASYNC16(db + c, pb + i * 8);                                   \
        }                                                                     \
    } while (0)

    LOAD_STAGE(0, 0);  CP_COMMIT();
    LOAD_STAGE(1, 64); CP_COMMIT();

    const int NITER = KTOT / 64;   // 48
    for (int kt = 0; kt < NITER; kt++) {
        if (kt + 2 < NITER) LOAD_STAGE((kt + 2) % 3, (kt + 2) * 64);
        CP_COMMIT();
        CP_WAIT2();
        __syncthreads();

        const uint32_t st = sb + (uint32_t)(kt % 3) * GSTG;
#pragma unroll
        for (int ks = 0; ks < 4; ks++) {
            uint32_t a0[4], a1[4], bf[4][4];
            uint32_t ac = (aC + ks * 32) ^ lX;
            uint32_t bc = (bC + ks * 32) ^ lX;
            ldmx4(a0, st + aBase + ac);
            ldmx4(a1, st + aBase + 2048 + ac);
#pragma unroll
            for (int jn = 0; jn < 4; jn++)
                ldmx4(bf[jn], st + bBase + jn * 2048 + bc);
#pragma unroll
            for (int j8 = 0; j8 < 8; j8++) {
                const uint32_t* bp = &bf[j8 >> 1][(j8 & 1) * 2];
                mma16816(acc[0][j8], a0, bp);
                mma16816(acc[1][j8], a1, bp);
            }
        }
        __syncthreads();
    }

    // Epilogue. acc mapping: rows (l>>2) + 8*half, cols (l&3)*2 + {0,1}
    const int mrow = bm + wm * 32 + (l >> 2);
    const int ncol0 = bn + wn * 64 + (l & 3) * 2;
#pragma unroll
    for (int im = 0; im < 2; im++) {
#pragma unroll
        for (int j8 = 0; j8 < 8; j8++) {
            int c = ncol0 + j8 * 8;
#pragma unroll
            for (int half = 0; half < 2; half++) {
                int m = mrow + im * 16 + half * 8;
                float2 v = make_float2(acc[im][j8][half * 2],
                                       acc[im][j8][half * 2 + 1]);
                if (MODE == 0) {
                    int which = c >> 10;
                    float* dst = (which == 0) ? g_q : (which == 1) ? g_k : g_v;
                    int h = (c & 1023) >> 6, d = c & 63;
                    int b = m >> 11, t = m & 2047;
                    *(float2*)(dst + ((size_t)((b << 4) + h) * PT + t) * PD + d) = v;
                } else {
                    *(float2*)(outp + (size_t)m * PC + c) = v;
                }
            }
        }
    }
#undef LOAD_STAGE
}

// ---------------------------------------------------------------------------
// Fast exp: FFMA-only (MUFU would bottleneck 67M exps).
// ---------------------------------------------------------------------------
__device__ __forceinline__ float fast_exp(float x) {
    float y = fmaxf(x * 1.4426950408889634f, -126.0f);
    float n = floorf(y);
    float f = y - n;
    float p = 0.0013333558f;
    p = fmaf(p, f, 0.0096181291f);
    p = fmaf(p, f, 0.0555041087f);
    p = fmaf(p, f, 0.2402265069f);
    p = fmaf(p, f, 0.6931471806f);
    p = fmaf(p, f, 1.0f);
    return p * __int_as_float(((int)n + 127) << 23);
}

// ---------------------------------------------------------------------------
// Causal flash attention, fp32 SIMT (proven); epilogue writes y in
// [hi | lo | hi] split form directly into g_ys for the out-projection.
// ---------------------------------------------------------------------------
#define APITCH 68
#define ATTN_SMEM_BYTES ((3 * 64 * APITCH + 3 * 64) * 4)

__global__ __launch_bounds__(256) void attn_kernel() {
    extern __shared__ float smem_raw[];
    float (*Qs)[APITCH] = (float(*)[APITCH])smem_raw;
    float (*KP)[APITCH] = (float(*)[APITCH])(smem_raw + 64 * APITCH);
    float (*Vs)[APITCH] = (float(*)[APITCH])(smem_raw + 2 * 64 * APITCH);
    float* m_s = smem_raw + 3 * 64 * APITCH;
    float* l_s = m_s + 64;
    float* corr_s = l_s + 64;

    const int tid = threadIdx.x;
    const int tx = tid & 15, ty = tid >> 4;
    const int bh = blockIdx.y;
    const int q0 = blockIdx.x << 6;
    const size_t base = (size_t)bh * PT * PD;
    const float* qg = g_q + base;
    const float* kg = g_k + base;
    const float* vg = g_v + base;

    {
        int r = tid >> 2;
        int dbase = (tid & 3) << 4;
        const float* row = qg + (size_t)(q0 + r) * PD + dbase;
#pragma unroll
        for (int i = 0; i < 16; i += 4) {
            float4 v = *(const float4*)(row + i);
            Qs[dbase + i + 0][r] = v.x;
            Qs[dbase + i + 1][r] = v.y;
            Qs[dbase + i + 2][r] = v.z;
            Qs[dbase + i + 3][r] = v.w;
        }
    }
    if (tid < 64) { m_s[tid] = -1e30f; l_s[tid] = 0.f; }

    float o[4][4];
#pragma unroll
    for (int i = 0; i < 4; i++)
#pragma unroll
        for (int j = 0; j < 4; j++) o[i][j] = 0.f;

    const int jmax = q0 >> 6;
    for (int jt = 0; jt <= jmax; jt++) {
        const int k0 = jt << 6;
        {
            int r = tid >> 2;
            int dbase = (tid & 3) << 4;
            const float* krow = kg + (size_t)(k0 + r) * PD + dbase;
            const float* vrow = vg + (size_t)(k0 + r) * PD + dbase;
#pragma unroll
            for (int i = 0; i < 16; i += 4) {
                float4 kv = *(const float4*)(krow + i);
                KP[dbase + i + 0][r] = kv.x;
                KP[dbase + i + 1][r] = kv.y;
                KP[dbase + i + 2][r] = kv.z;
                KP[dbase + i + 3][r] = kv.w;
                *(float4*)&Vs[r][dbase + i] = *(const float4*)(vrow + i);
            }
        }
        __syncthreads();

        float s[4][4];
#pragma unroll
        for (int i = 0; i < 4; i++)
#pragma unroll
            for (int j = 0; j < 4; j++) s[i][j] = 0.f;
#pragma unroll 16
        for (int d = 0; d < 64; d++) {
            const float4 aq = *(const float4*)&Qs[d][ty << 2];
            const float4 bk = *(const float4*)&KP[d][tx << 2];
            const float av[4] = {aq.x, aq.y, aq.z, aq.w};
            const float bv[4] = {bk.x, bk.y, bk.z, bk.w};
#pragma unroll
            for (int i = 0; i < 4; i++)
#pragma unroll
                for (int j = 0; j < 4; j++) s[i][j] = fmaf(av[i], bv[j], s[i][j]);
        }
        __syncthreads();

        const float scale = 0.125f;
#pragma unroll
        for (int i = 0; i < 4; i++) {
            int qi = q0 + (ty << 2) + i;
#pragma unroll
            for (int j = 0; j < 4; j++) {
                int ki = k0 + (tx << 2) + j;
                float v = s[i][j] * scale;
                if (ki > qi) v = -1e30f;
                KP[(tx << 2) + j][(ty << 2) + i] = v;
            }
        }
        __syncthreads();

        {
            int r = tid >> 2, p = tid & 3;
            int cbase = p << 4;
            float tmax = -1e30f;
#pragma unroll
            for (int c = 0; c < 16; c++) tmax = fmaxf(tmax, KP[cbase + c][r]);
            tmax = fmaxf(tmax, __shfl_xor_sync(0xffffffffu, tmax, 1));
            tmax = fmaxf(tmax, __shfl_xor_sync(0xffffffffu, tmax, 2));
            float mold = m_s[r];
            float newm = fmaxf(mold, tmax);
            float psum = 0.f;
#pragma unroll
            for (int c = 0; c < 16; c++) {
                float pv = fast_exp(KP[cbase + c][r] - newm);
                KP[cbase + c][r] = pv;
                psum += pv;
            }
            psum += __shfl_xor_sync(0xffffffffu, psum, 1);
            psum += __shfl_xor_sync(0xffffffffu, psum, 2);
            if (p == 0) {
                float cr = fast_exp(mold - newm);
                corr_s[r] = cr;
                l_s[r] = l_s[r] * cr + psum;
                m_s[r] = newm;
            }
        }
        __syncthreads();

#pragma unroll
        for (int i = 0; i < 4; i++) {
            float cf = corr_s[(ty << 2) + i];
#pragma unroll
            for (int j = 0; j < 4; j++) o[i][j] *= cf;
        }
#pragma unroll 16
        for (int kk = 0; kk < 64; kk++) {
            const float4 ap = *(const float4*)&KP[kk][ty << 2];
            const float4 bp = *(const float4*)&Vs[kk][tx << 2];
            const float av[4] = {ap.x, ap.y, ap.z, ap.w};
            const float bv[4] = {bp.x, bp.y, bp.z, bp.w};
#pragma unroll
            for (int i = 0; i < 4; i++)
#pragma unroll
                for (int j = 0; j < 4; j++) o[i][j] = fmaf(av[i], bv[j], o[i][j]);
        }
        __syncthreads();
    }

    // Epilogue: normalize + [hi|lo|hi] split store into g_ys
    const int b = bh >> 4;
    const int h = bh & 15;
#pragma unroll
    for (int i = 0; i < 4; i++) {
        int q = q0 + (ty << 2) + i;
        float inv = 1.f / l_s[(ty << 2) + i];
        size_t rb = ((size_t)b * PT + q) * KTOT + h * PD;
#pragma unroll
        for (int j = 0; j < 4; j++) {
            int d = (tx << 2) + j;
            float v = o[i][j] * inv;
            uint32_t u = __float_as_uint(v);
            unsigned short hb = (unsigned short)(u >> 16);
            __nv_bfloat16 lb =
                __float2bfloat16(v - __uint_as_float(u & 0xFFFF0000u));
            ((unsigned short*)g_ys)[rb + d] = hb;           // seg0 hi
            g_ys[rb + 1024 + d] = lb;                       // seg1 lo
            ((unsigned short*)g_ys)[rb + 2048 + d] = hb;    // seg2 hi
        }
    }
}

// ---------------------------------------------------------------------------
extern "C" void kernel_launch(void* const* d_in, const int* in_sizes, int n_in,
                              void* d_out, int out_size) {
    const float* x  = (const float*)d_in[0];
    const float* wq = (const float*)d_in[1];
    const float* wk = (const float*)d_in[2];
    const float* wv = (const float*)d_in[3];
    const float* wo = (const float*)d_in[4];
    float* out = (float*)d_out;

    cudaFuncSetAttribute(attn_kernel,
                         cudaFuncAttributeMaxDynamicSharedMemorySize,
                         ATTN_SMEM_BYTES);
    cudaFuncSetAttribute(gemm_kernel<0>,
                         cudaFuncAttributeMaxDynamicSharedMemorySize, GEMM_SMEM);
    cudaFuncSetAttribute(gemm_kernel<1>,
                         cudaFuncAttributeMaxDynamicSharedMemorySize, GEMM_SMEM);

    const int n4x = PM * PC / 4;      // 1048576
    const int n4w = PC * PC / 4;      // 262144
    split_kernel<<<n4x / 256, 256>>>(x, 0, 0, n4x);
    split_kernel<<<n4w / 256, 256>>>(wq, 1, 0, n4w);
    split_kernel<<<n4w / 256, 256>>>(wk, 1, PC, n4w);
    split_kernel<<<n4w / 256, 256>>>(wv, 1, 2 * PC, n4w);
    transpose_split_wo<<<dim3(32, 32), dim3(32, 8)>>>(wo);

    gemm_kernel<0><<<dim3(PM / 128, 3 * PC / 128), 256, GEMM_SMEM>>>(nullptr);
    attn_kernel<<<dim3(PT / 64, PB * PH), 256, ATTN_SMEM_BYTES>>>();
    gemm_kernel<1><<<dim3(PM / 128, PC / 128), 256, GEMM_SMEM>>>(out);
}